// round 6
// baseline (speedup 1.0000x reference)
#include <cuda_runtime.h>
#include <cuda_fp16.h>
#include <cuda_bf16.h>

#define NN 50000
#define EE 800000
#define DD 128
#define OO 64
#define LL 3

// ---------------- scratch (device globals) ----------------
__device__ __half g_hx[NN * DD];      // x converted to fp16
__device__ __half g_h0[NN * DD];
__device__ __half g_h1[NN * DD];
__device__ __half g_agg0[NN * DD];    // (1-a)/deg * sum_{src->dst}
__device__ __half g_agg1[NN * DD];    // a/deg * sum_{dst->src}
__device__ __half g_hmax[NN * DD];
__device__ __half g_Wt[LL * 3 * DD * DD];   // weights fp16, transposed [mat][n][k]

__device__ int g_deg0[NN];
__device__ int g_deg1[NN];
__device__ int g_rp0[NN + 1];
__device__ int g_rp1[NN + 1];
__device__ int g_cur0[NN];
__device__ int g_cur1[NN];
__device__ int g_col0[EE];            // CSR by dst, values = src
__device__ int g_col1[EE];            // CSR by src, values = dst

// ---------------- prep: convert x, transpose+convert weights ----------------
__global__ void convert_x_kernel(const float* __restrict__ x, int total4) {
    int i = blockIdx.x * blockDim.x + threadIdx.x;
    if (i >= total4) return;
    float4 v = ((const float4*)x)[i];
    __half2 h0 = __floats2half2_rn(v.x, v.y);
    __half2 h1 = __floats2half2_rn(v.z, v.w);
    uint2 u;
    u.x = *(unsigned*)&h0;
    u.y = *(unsigned*)&h1;
    ((uint2*)g_hx)[i] = u;
}

__global__ void prep_weights_kernel(const float* __restrict__ Wself,
                                    const float* __restrict__ Wstd,
                                    const float* __restrict__ Wdts) {
    int idx = blockIdx.x * blockDim.x + threadIdx.x;
    if (idx >= LL * 3 * DD * DD) return;
    int mat = idx >> 14;          // l*3+s
    int r = (idx >> 7) & 127;     // k (input dim)
    int c = idx & 127;            // n (output dim)
    int l = mat / 3, s = mat % 3;
    const float* W = (s == 0) ? Wself : (s == 1) ? Wstd : Wdts;
    float v = W[(size_t)l * DD * DD + r * DD + c];
    g_Wt[(size_t)mat * DD * DD + c * DD + r] = __float2half(v);
}

// ---------------- CSR build ----------------
__global__ void zero_deg_kernel(int n) {
    int i = blockIdx.x * blockDim.x + threadIdx.x;
    if (i < n) { g_deg0[i] = 0; g_deg1[i] = 0; }
}

__global__ void count_kernel(const int* __restrict__ ei, int E) {
    int e = blockIdx.x * blockDim.x + threadIdx.x;
    if (e >= E) return;
    int src = ei[e];
    int dst = ei[E + e];
    atomicAdd(&g_deg0[dst], 1);
    atomicAdd(&g_deg1[src], 1);
}

__global__ void scan_kernel(int n) {
    const int* deg = (blockIdx.x == 0) ? g_deg0 : g_deg1;
    int* rp = (blockIdx.x == 0) ? g_rp0 : g_rp1;
    int* cur = (blockIdx.x == 0) ? g_cur0 : g_cur1;

    __shared__ int sums[1024];
    int t = threadIdx.x;
    int chunk = (n + 1023) / 1024;
    int begin = t * chunk;
    int end = min(begin + chunk, n);
    int s = 0;
    for (int i = begin; i < end; i++) s += deg[i];
    sums[t] = s;
    __syncthreads();
    for (int off = 1; off < 1024; off <<= 1) {
        int v = (t >= off) ? sums[t - off] : 0;
        __syncthreads();
        sums[t] += v;
        __syncthreads();
    }
    int prefix = (t == 0) ? 0 : sums[t - 1];
    for (int i = begin; i < end; i++) {
        rp[i] = prefix;
        cur[i] = prefix;
        prefix += deg[i];
    }
    if (t == 1023) rp[n] = prefix;
}

__global__ void fill_kernel(const int* __restrict__ ei, int E) {
    int e = blockIdx.x * blockDim.x + threadIdx.x;
    if (e >= E) return;
    int src = ei[e];
    int dst = ei[E + e];
    int p0 = atomicAdd(&g_cur0[dst], 1);
    g_col0[p0] = src;
    int p1 = atomicAdd(&g_cur1[src], 1);
    g_col1[p1] = dst;
}

// ---------------- aggregation (fp16): one warp per (node, direction) --------
__global__ void agg_kernel(const __half* __restrict__ h,
                           const float* __restrict__ alpha, int M) {
    int gw = (blockIdx.x * blockDim.x + threadIdx.x) >> 5;
    int node = gw >> 1;
    int dir = gw & 1;
    if (node >= M) return;
    int lane = threadIdx.x & 31;
    int base = lane * 4;   // halves
    float a = alpha[0];

    const int* rp  = dir ? g_rp1  : g_rp0;
    const int* col = dir ? g_col1 : g_col0;
    __half* out    = dir ? g_agg1 : g_agg0;
    float coef     = dir ? a : (1.f - a);

    int s = rp[node], e = rp[node + 1];
    float4 acc = make_float4(0.f, 0.f, 0.f, 0.f);
    int i = s;
    for (; i + 3 < e; i += 4) {
        int n0 = col[i],     n1 = col[i + 1];
        int n2 = col[i + 2], n3 = col[i + 3];
        uint2 u0 = *(const uint2*)(h + (size_t)n0 * DD + base);
        uint2 u1 = *(const uint2*)(h + (size_t)n1 * DD + base);
        uint2 u2 = *(const uint2*)(h + (size_t)n2 * DD + base);
        uint2 u3 = *(const uint2*)(h + (size_t)n3 * DD + base);
        float2 f;
        f = __half22float2(*(__half2*)&u0.x); acc.x += f.x; acc.y += f.y;
        f = __half22float2(*(__half2*)&u0.y); acc.z += f.x; acc.w += f.y;
        f = __half22float2(*(__half2*)&u1.x); acc.x += f.x; acc.y += f.y;
        f = __half22float2(*(__half2*)&u1.y); acc.z += f.x; acc.w += f.y;
        f = __half22float2(*(__half2*)&u2.x); acc.x += f.x; acc.y += f.y;
        f = __half22float2(*(__half2*)&u2.y); acc.z += f.x; acc.w += f.y;
        f = __half22float2(*(__half2*)&u3.x); acc.x += f.x; acc.y += f.y;
        f = __half22float2(*(__half2*)&u3.y); acc.z += f.x; acc.w += f.y;
    }
    for (; i < e; i++) {
        int n0 = col[i];
        uint2 u0 = *(const uint2*)(h + (size_t)n0 * DD + base);
        float2 f;
        f = __half22float2(*(__half2*)&u0.x); acc.x += f.x; acc.y += f.y;
        f = __half22float2(*(__half2*)&u0.y); acc.z += f.x; acc.w += f.y;
    }
    float sc = coef / fmaxf((float)(e - s), 1.f);
    __half2 o0 = __floats2half2_rn(acc.x * sc, acc.y * sc);
    __half2 o1 = __floats2half2_rn(acc.z * sc, acc.w * sc);
    uint2 u;
    u.x = *(unsigned*)&o0;
    u.y = *(unsigned*)&o1;
    *(uint2*)(out + (size_t)node * DD + base) = u;
}

// ---------------- fp16 tensor-core layer GEMM (ldmatrix fragments) ----------
// [h|agg0|agg1](Mx384 fp16) @ Wt(384x128 fp16, pre-transposed [n][k])
// 256 threads = 8 warps (4x2), warp tile 32x64, mma.m16n8k16.f16.f16.f32,
// BK=32, 12 chunks, double-buffered smem, ldmatrix.x4 fragment loads.
#define SA 40   // smem row stride in halves

__device__ __forceinline__ void ldsm_x4(unsigned& r0, unsigned& r1,
                                        unsigned& r2, unsigned& r3,
                                        const __half* p) {
    unsigned addr = (unsigned)__cvta_generic_to_shared(p);
    asm volatile("ldmatrix.sync.aligned.m8n8.x4.shared.b16 {%0,%1,%2,%3}, [%4];"
                 : "=r"(r0), "=r"(r1), "=r"(r2), "=r"(r3) : "r"(addr));
}

__global__ __launch_bounds__(256) void gemm_layer_f16(
    const __half* __restrict__ A0,
    const __half* __restrict__ Wt,   // layer base (3 mats)
    const float* __restrict__ bs0,
    const float* __restrict__ bs1,
    const float* __restrict__ bs2,
    const float* __restrict__ alpha,
    __half* __restrict__ Hout,
    int firstLayer, int M)
{
    __shared__ __align__(16) __half As[2][128 * SA];
    __shared__ __align__(16) __half Bs[2][128 * SA];
    __shared__ float bias_s[DD];

    int tid = threadIdx.x;
    int block_row = blockIdx.x * 128;
    int warpId = tid >> 5;
    int lane = tid & 31;
    int g = lane >> 2;
    int t = lane & 3;
    int warp_row = warpId & 3;
    int warp_col = warpId >> 2;

    if (tid < DD) {
        float a = alpha[0];
        bias_s[tid] = bs0[tid] + (1.f - a) * bs1[tid] + a * bs2[tid];
    }

    // ldmatrix lane address components
    int lm_row8 = lane & 7;
    int a_roff = lm_row8 + ((lane >> 3) & 1) * 8;   // row within 16
    int a_koff = (lane >> 4) * 8;                   // 0 or 8
    int b_noff = lm_row8 + ((lane >> 4) & 1) * 8;   // n within 16
    int b_koff = ((lane >> 3) & 1) * 8;             // 0 or 8

    float acc[2][8][4];
    #pragma unroll
    for (int mt = 0; mt < 2; mt++)
        #pragma unroll
        for (int nt = 0; nt < 8; nt++)
            #pragma unroll
            for (int r = 0; r < 4; r++) acc[mt][nt][r] = 0.f;

    const __half* Aseg[3] = { A0, g_agg0, g_agg1 };

    int l_row = tid >> 2;          // 0..63
    int l_kq = (tid & 3) * 8;      // halves: 0,8,16,24

    uint4 ra[2], rb[2];

    auto load_chunk = [&](int c) {
        int seg = c >> 2;
        int kl = (c & 3) * 32;
        const __half* A = Aseg[seg];
        const __half* B = Wt + (size_t)seg * DD * DD;
        #pragma unroll
        for (int j = 0; j < 2; j++) {
            int row = l_row + j * 64;
            int gr = block_row + row;
            ra[j] = (gr < M) ? *(const uint4*)(A + (size_t)gr * DD + kl + l_kq)
                             : make_uint4(0u, 0u, 0u, 0u);
            rb[j] = *(const uint4*)(B + (size_t)row * DD + kl + l_kq);
        }
    };
    auto store_chunk = [&](int buf) {
        #pragma unroll
        for (int j = 0; j < 2; j++) {
            int row = l_row + j * 64;
            *(uint4*)&As[buf][row * SA + l_kq] = ra[j];
            *(uint4*)&Bs[buf][row * SA + l_kq] = rb[j];
        }
    };

    load_chunk(0);
    store_chunk(0);
    __syncthreads();

    #pragma unroll 1
    for (int c = 0; c < 12; c++) {
        int buf = c & 1;
        if (c < 11) load_chunk(c + 1);

        #pragma unroll
        for (int ks = 0; ks < 2; ks++) {
            int k0 = ks * 16;
            unsigned af[2][4];
            #pragma unroll
            for (int mt = 0; mt < 2; mt++) {
                int mrow = warp_row * 32 + mt * 16;
                ldsm_x4(af[mt][0], af[mt][1], af[mt][2], af[mt][3],
                        &As[buf][(mrow + a_roff) * SA + k0 + a_koff]);
            }
            unsigned bf[8][2];
            #pragma unroll
            for (int np = 0; np < 4; np++) {
                int n0 = warp_col * 64 + np * 16;
                ldsm_x4(bf[np * 2][0], bf[np * 2][1], bf[np * 2 + 1][0], bf[np * 2 + 1][1],
                        &Bs[buf][(n0 + b_noff) * SA + k0 + b_koff]);
            }
            #pragma unroll
            for (int mt = 0; mt < 2; mt++)
                #pragma unroll
                for (int nt = 0; nt < 8; nt++) {
                    asm volatile(
                        "mma.sync.aligned.m16n8k16.row.col.f32.f16.f16.f32 "
                        "{%0,%1,%2,%3}, {%4,%5,%6,%7}, {%8,%9}, {%0,%1,%2,%3};"
                        : "+f"(acc[mt][nt][0]), "+f"(acc[mt][nt][1]),
                          "+f"(acc[mt][nt][2]), "+f"(acc[mt][nt][3])
                        : "r"(af[mt][0]), "r"(af[mt][1]), "r"(af[mt][2]), "r"(af[mt][3]),
                          "r"(bf[nt][0]), "r"(bf[nt][1]));
                }
        }
        if (c < 11) {
            store_chunk(buf ^ 1);
            __syncthreads();
        }
    }

    // epilogue: bias + relu + store h(fp16) + JK max(fp16)
    #pragma unroll
    for (int mt = 0; mt < 2; mt++) {
        #pragma unroll
        for (int nt = 0; nt < 8; nt++) {
            int c0 = warp_col * 64 + nt * 8 + 2 * t;
            float b0v = bias_s[c0];
            float b1v = bias_s[c0 + 1];
            #pragma unroll
            for (int rr = 0; rr < 2; rr++) {
                int r = block_row + warp_row * 32 + mt * 16 + g + rr * 8;
                if (r < M) {
                    float v0 = fmaxf(acc[mt][nt][rr * 2 + 0] + b0v, 0.f);
                    float v1 = fmaxf(acc[mt][nt][rr * 2 + 1] + b1v, 0.f);
                    __half2 hv = __floats2half2_rn(v0, v1);
                    *(__half2*)(Hout + (size_t)r * DD + c0) = hv;
                    __half2* mp = (__half2*)(g_hmax + (size_t)r * DD + c0);
                    if (firstLayer) {
                        *mp = hv;
                    } else {
                        *mp = __hmax2(*mp, hv);
                    }
                }
            }
        }
    }
}

// ---------------- final linear: hmax(fp16, Mx128) @ Wlin(fp32 128x64) + blin ----
__global__ __launch_bounds__(256) void final_gemm_kernel(
    const float* __restrict__ W, const float* __restrict__ b,
    float* __restrict__ out, int M)
{
    __shared__ __align__(16) float Ws[DD * OO];
    __shared__ __align__(16) float As[16][DD];

    int tid = threadIdx.x;
    for (int i = tid; i < DD * OO / 4; i += 256)
        ((float4*)Ws)[i] = ((const float4*)W)[i];

    int row0 = blockIdx.x * 16;
    for (int i = tid; i < 512; i += 256) {
        int r = i >> 5;
        int c4 = (i & 31) * 4;
        int gr = row0 + r;
        float4 v = make_float4(0.f, 0.f, 0.f, 0.f);
        if (gr < M) {
            uint2 u = *(const uint2*)(g_hmax + (size_t)gr * DD + c4);
            float2 f0 = __half22float2(*(__half2*)&u.x);
            float2 f1 = __half22float2(*(__half2*)&u.y);
            v = make_float4(f0.x, f0.y, f1.x, f1.y);
        }
        *(float4*)&As[r][c4] = v;
    }
    __syncthreads();

    int col = tid & 63;
    int rgrp = tid >> 6;
    float acc[4] = { 0.f, 0.f, 0.f, 0.f };
    #pragma unroll 4
    for (int k = 0; k < DD; k++) {
        float w = Ws[k * OO + col];
        #pragma unroll
        for (int i = 0; i < 4; i++)
            acc[i] += As[rgrp + i * 4][k] * w;
    }
    float bb = b[col];
    #pragma unroll
    for (int i = 0; i < 4; i++) {
        int r = row0 + rgrp + i * 4;
        if (r < M) out[(size_t)r * OO + col] = acc[i] + bb;
    }
}

// ---------------- launch ----------------
extern "C" void kernel_launch(void* const* d_in, const int* in_sizes, int n_in,
                              void* d_out, int out_size) {
    const float* x     = (const float*)d_in[0];
    const int*   ei    = (const int*)d_in[1];
    const float* Wself = (const float*)d_in[2];
    const float* bself = (const float*)d_in[3];
    const float* Wstd  = (const float*)d_in[4];
    const float* bstd  = (const float*)d_in[5];
    const float* Wdts  = (const float*)d_in[6];
    const float* bdts  = (const float*)d_in[7];
    const float* Wlin  = (const float*)d_in[8];
    const float* blin  = (const float*)d_in[9];
    const float* alpha = (const float*)d_in[10];

    int M = in_sizes[0] / DD;        // 50000
    int E = in_sizes[1] / 2;         // 800000

    __half* hx; cudaGetSymbolAddress((void**)&hx, g_hx);
    __half* h0; cudaGetSymbolAddress((void**)&h0, g_h0);
    __half* h1; cudaGetSymbolAddress((void**)&h1, g_h1);
    __half* wt; cudaGetSymbolAddress((void**)&wt, g_Wt);

    // CSR build
    zero_deg_kernel<<<(M + 255) / 256, 256>>>(M);
    count_kernel<<<(E + 255) / 256, 256>>>(ei, E);
    scan_kernel<<<2, 1024>>>(M);
    fill_kernel<<<(E + 255) / 256, 256>>>(ei, E);

    int total4 = M * DD / 4;
    convert_x_kernel<<<(total4 + 255) / 256, 256>>>(x, total4);

    // layers
    const __half* cur = hx;
    __half* bufs[2] = { h0, h1 };
    int gemm_grid = (M + 127) / 128;
    int agg_grid = (M * 64 + 255) / 256;   // one warp per (node, direction)
    for (int l = 0; l < LL; l++) {
        agg_kernel<<<agg_grid, 256>>>(cur, alpha, M);
        if (l == 0)
            prep_weights_kernel<<<(LL * 3 * DD * DD + 255) / 256, 256>>>(Wself, Wstd, Wdts);
        __half* outb = bufs[l & 1];
        gemm_layer_f16<<<gemm_grid, 256>>>(
            cur,
            wt + (size_t)l * 3 * DD * DD,
            bself + (size_t)l * DD,
            bstd  + (size_t)l * DD,
            bdts  + (size_t)l * DD,
            alpha, outb, (l == 0) ? 1 : 0, M);
        cur = outb;
    }

    // final linear
    final_gemm_kernel<<<(M + 15) / 16, 256>>>(Wlin, blin, (float*)d_out, M);
}

// round 7
// speedup vs baseline: 1.0580x; 1.0580x over previous
#include <cuda_runtime.h>
#include <cuda_fp16.h>
#include <cuda_bf16.h>

#define NN 50000
#define EE 800000
#define DD 128
#define OO 64
#define LL 3

// ---------------- scratch (device globals) ----------------
__device__ __half g_hx[NN * DD];      // x converted to fp16
__device__ __half g_h0[NN * DD];
__device__ __half g_h1[NN * DD];
__device__ __half g_agg0[NN * DD];    // (1-a)/deg * sum_{src->dst}
__device__ __half g_agg1[NN * DD];    // a/deg * sum_{dst->src}
__device__ __half g_hmax[NN * DD];
__device__ __half g_Wt[LL * 3 * DD * DD];   // weights fp16, transposed [mat][n][k]

__device__ int g_deg0[NN];
__device__ int g_deg1[NN];
__device__ int g_rp0[NN + 1];
__device__ int g_rp1[NN + 1];
__device__ int g_cur0[NN];
__device__ int g_cur1[NN];
__device__ int g_col0[EE];            // CSR by dst, values = src
__device__ int g_col1[EE];            // CSR by src, values = dst

// ---------------- prep: transpose+convert weights ----------------
__global__ void prep_weights_kernel(const float* __restrict__ Wself,
                                    const float* __restrict__ Wstd,
                                    const float* __restrict__ Wdts) {
    int idx = blockIdx.x * blockDim.x + threadIdx.x;
    if (idx >= LL * 3 * DD * DD) return;
    int mat = idx >> 14;          // l*3+s
    int r = (idx >> 7) & 127;     // k (input dim)
    int c = idx & 127;            // n (output dim)
    int l = mat / 3, s = mat % 3;
    const float* W = (s == 0) ? Wself : (s == 1) ? Wstd : Wdts;
    float v = W[(size_t)l * DD * DD + r * DD + c];
    g_Wt[(size_t)mat * DD * DD + c * DD + r] = __float2half(v);
}

// ---------------- CSR build ----------------
__global__ void count_kernel(const int* __restrict__ ei, int E) {
    int e = blockIdx.x * blockDim.x + threadIdx.x;
    if (e >= E) return;
    int src = ei[e];
    int dst = ei[E + e];
    atomicAdd(&g_deg0[dst], 1);
    atomicAdd(&g_deg1[src], 1);
}

__global__ void scan_kernel(int n) {
    const int* deg = (blockIdx.x == 0) ? g_deg0 : g_deg1;
    int* rp = (blockIdx.x == 0) ? g_rp0 : g_rp1;
    int* cur = (blockIdx.x == 0) ? g_cur0 : g_cur1;

    __shared__ int sums[1024];
    int t = threadIdx.x;
    int chunk = (n + 1023) / 1024;
    int begin = t * chunk;
    int end = min(begin + chunk, n);
    int s = 0;
    for (int i = begin; i < end; i++) s += deg[i];
    sums[t] = s;
    __syncthreads();
    for (int off = 1; off < 1024; off <<= 1) {
        int v = (t >= off) ? sums[t - off] : 0;
        __syncthreads();
        sums[t] += v;
        __syncthreads();
    }
    int prefix = (t == 0) ? 0 : sums[t - 1];
    for (int i = begin; i < end; i++) {
        rp[i] = prefix;
        cur[i] = prefix;
        prefix += deg[i];
    }
    if (t == 1023) rp[n] = prefix;
}

// fused: blocks [0, fillBlocks) do CSR fill; rest convert x -> fp16
__global__ void fill_convert_kernel(const int* __restrict__ ei, int E,
                                    const float* __restrict__ x, int total4,
                                    int fillBlocks) {
    if ((int)blockIdx.x < fillBlocks) {
        int e = blockIdx.x * blockDim.x + threadIdx.x;
        if (e >= E) return;
        int src = ei[e];
        int dst = ei[E + e];
        int p0 = atomicAdd(&g_cur0[dst], 1);
        g_col0[p0] = src;
        int p1 = atomicAdd(&g_cur1[src], 1);
        g_col1[p1] = dst;
    } else {
        int i = (blockIdx.x - fillBlocks) * blockDim.x + threadIdx.x;
        if (i >= total4) return;
        float4 v = ((const float4*)x)[i];
        __half2 h0 = __floats2half2_rn(v.x, v.y);
        __half2 h1 = __floats2half2_rn(v.z, v.w);
        uint2 u;
        u.x = *(unsigned*)&h0;
        u.y = *(unsigned*)&h1;
        ((uint2*)g_hx)[i] = u;
    }
}

// ---------------- aggregation (fp16): one warp per node, unroll 4 ----------
__global__ void agg_kernel(const __half* __restrict__ h,
                           const float* __restrict__ alpha, int M) {
    int gw = (blockIdx.x * blockDim.x + threadIdx.x) >> 5;
    if (gw >= M) return;
    int lane = threadIdx.x & 31;
    int base = lane * 4;   // halves
    float a = alpha[0];

    #pragma unroll
    for (int dir = 0; dir < 2; dir++) {
        const int* rp  = dir ? g_rp1  : g_rp0;
        const int* col = dir ? g_col1 : g_col0;
        __half* out    = dir ? g_agg1 : g_agg0;
        float coef     = dir ? a : (1.f - a);

        int s = rp[gw], e = rp[gw + 1];
        float4 acc = make_float4(0.f, 0.f, 0.f, 0.f);
        int i = s;
        for (; i + 3 < e; i += 4) {
            int n0 = col[i],     n1 = col[i + 1];
            int n2 = col[i + 2], n3 = col[i + 3];
            uint2 u0 = *(const uint2*)(h + (size_t)n0 * DD + base);
            uint2 u1 = *(const uint2*)(h + (size_t)n1 * DD + base);
            uint2 u2 = *(const uint2*)(h + (size_t)n2 * DD + base);
            uint2 u3 = *(const uint2*)(h + (size_t)n3 * DD + base);
            float2 f;
            f = __half22float2(*(__half2*)&u0.x); acc.x += f.x; acc.y += f.y;
            f = __half22float2(*(__half2*)&u0.y); acc.z += f.x; acc.w += f.y;
            f = __half22float2(*(__half2*)&u1.x); acc.x += f.x; acc.y += f.y;
            f = __half22float2(*(__half2*)&u1.y); acc.z += f.x; acc.w += f.y;
            f = __half22float2(*(__half2*)&u2.x); acc.x += f.x; acc.y += f.y;
            f = __half22float2(*(__half2*)&u2.y); acc.z += f.x; acc.w += f.y;
            f = __half22float2(*(__half2*)&u3.x); acc.x += f.x; acc.y += f.y;
            f = __half22float2(*(__half2*)&u3.y); acc.z += f.x; acc.w += f.y;
        }
        for (; i < e; i++) {
            int n0 = col[i];
            uint2 u0 = *(const uint2*)(h + (size_t)n0 * DD + base);
            float2 f;
            f = __half22float2(*(__half2*)&u0.x); acc.x += f.x; acc.y += f.y;
            f = __half22float2(*(__half2*)&u0.y); acc.z += f.x; acc.w += f.y;
        }
        float sc = coef / fmaxf((float)(e - s), 1.f);
        __half2 o0 = __floats2half2_rn(acc.x * sc, acc.y * sc);
        __half2 o1 = __floats2half2_rn(acc.z * sc, acc.w * sc);
        uint2 u;
        u.x = *(unsigned*)&o0;
        u.y = *(unsigned*)&o1;
        *(uint2*)(out + (size_t)gw * DD + base) = u;
    }
}

// ---------------- fp16 tensor-core layer GEMM ----------------
// [h|agg0|agg1](Mx384 fp16) @ Wt(384x128 fp16, pre-transposed [n][k])
// 256 threads = 8 warps (4x2), warp tile 32x64, mma.m16n8k16.f16.f16.f32,
// BK=32, 12 chunks, double-buffered smem, 1 sync/chunk.
#define SA 40   // smem row stride in halves

__global__ __launch_bounds__(256) void gemm_layer_f16(
    const __half* __restrict__ A0,
    const __half* __restrict__ Wt,   // layer base (3 mats)
    const float* __restrict__ bs0,
    const float* __restrict__ bs1,
    const float* __restrict__ bs2,
    const float* __restrict__ alpha,
    __half* __restrict__ Hout,
    int firstLayer, int M)
{
    __shared__ __align__(16) __half As[2][128 * SA];
    __shared__ __align__(16) __half Bs[2][128 * SA];
    __shared__ float bias_s[DD];

    int tid = threadIdx.x;
    int block_row = blockIdx.x * 128;
    int warpId = tid >> 5;
    int lane = tid & 31;
    int g = lane >> 2;
    int t = lane & 3;
    int warp_row = warpId & 3;
    int warp_col = warpId >> 2;

    if (tid < DD) {
        float a = alpha[0];
        bias_s[tid] = bs0[tid] + (1.f - a) * bs1[tid] + a * bs2[tid];
    }

    float acc[2][8][4];
    #pragma unroll
    for (int mt = 0; mt < 2; mt++)
        #pragma unroll
        for (int nt = 0; nt < 8; nt++)
            #pragma unroll
            for (int r = 0; r < 4; r++) acc[mt][nt][r] = 0.f;

    const __half* Aseg[3] = { A0, g_agg0, g_agg1 };

    int l_row = tid >> 2;          // 0..63
    int l_kq = (tid & 3) * 8;      // halves: 0,8,16,24

    uint4 ra[2], rb[2];

    auto load_chunk = [&](int c) {
        int seg = c >> 2;
        int kl = (c & 3) * 32;
        const __half* A = Aseg[seg];
        const __half* B = Wt + (size_t)seg * DD * DD;
        #pragma unroll
        for (int j = 0; j < 2; j++) {
            int row = l_row + j * 64;
            int gr = block_row + row;
            ra[j] = (gr < M) ? *(const uint4*)(A + (size_t)gr * DD + kl + l_kq)
                             : make_uint4(0u, 0u, 0u, 0u);
            rb[j] = *(const uint4*)(B + (size_t)row * DD + kl + l_kq);
        }
    };
    auto store_chunk = [&](int buf) {
        #pragma unroll
        for (int j = 0; j < 2; j++) {
            int row = l_row + j * 64;
            *(uint4*)&As[buf][row * SA + l_kq] = ra[j];
            *(uint4*)&Bs[buf][row * SA + l_kq] = rb[j];
        }
    };

    load_chunk(0);
    store_chunk(0);
    __syncthreads();

    #pragma unroll 1
    for (int c = 0; c < 12; c++) {
        int buf = c & 1;
        if (c < 11) load_chunk(c + 1);

        #pragma unroll
        for (int ks = 0; ks < 2; ks++) {
            int k0 = ks * 16;
            unsigned af[2][4];
            #pragma unroll
            for (int mt = 0; mt < 2; mt++) {
                int mrow = warp_row * 32 + mt * 16;
                const __half* base = &As[buf][0];
                af[mt][0] = *(const unsigned*)&base[(mrow + g) * SA + k0 + 2 * t];
                af[mt][1] = *(const unsigned*)&base[(mrow + g + 8) * SA + k0 + 2 * t];
                af[mt][2] = *(const unsigned*)&base[(mrow + g) * SA + k0 + 8 + 2 * t];
                af[mt][3] = *(const unsigned*)&base[(mrow + g + 8) * SA + k0 + 8 + 2 * t];
            }
            unsigned bf[8][2];
            #pragma unroll
            for (int nt = 0; nt < 8; nt++) {
                int n = warp_col * 64 + nt * 8 + g;
                const __half* base = &Bs[buf][0];
                bf[nt][0] = *(const unsigned*)&base[n * SA + k0 + 2 * t];
                bf[nt][1] = *(const unsigned*)&base[n * SA + k0 + 8 + 2 * t];
            }
            #pragma unroll
            for (int mt = 0; mt < 2; mt++)
                #pragma unroll
                for (int nt = 0; nt < 8; nt++) {
                    asm volatile(
                        "mma.sync.aligned.m16n8k16.row.col.f32.f16.f16.f32 "
                        "{%0,%1,%2,%3}, {%4,%5,%6,%7}, {%8,%9}, {%0,%1,%2,%3};"
                        : "+f"(acc[mt][nt][0]), "+f"(acc[mt][nt][1]),
                          "+f"(acc[mt][nt][2]), "+f"(acc[mt][nt][3])
                        : "r"(af[mt][0]), "r"(af[mt][1]), "r"(af[mt][2]), "r"(af[mt][3]),
                          "r"(bf[nt][0]), "r"(bf[nt][1]));
                }
        }
        if (c < 11) {
            store_chunk(buf ^ 1);
            __syncthreads();
        }
    }

    // epilogue: bias + relu + store h(fp16) + JK max(fp16)
    #pragma unroll
    for (int mt = 0; mt < 2; mt++) {
        #pragma unroll
        for (int nt = 0; nt < 8; nt++) {
            int c0 = warp_col * 64 + nt * 8 + 2 * t;
            float b0v = bias_s[c0];
            float b1v = bias_s[c0 + 1];
            #pragma unroll
            for (int rr = 0; rr < 2; rr++) {
                int r = block_row + warp_row * 32 + mt * 16 + g + rr * 8;
                if (r < M) {
                    float v0 = fmaxf(acc[mt][nt][rr * 2 + 0] + b0v, 0.f);
                    float v1 = fmaxf(acc[mt][nt][rr * 2 + 1] + b1v, 0.f);
                    __half2 hv = __floats2half2_rn(v0, v1);
                    *(__half2*)(Hout + (size_t)r * DD + c0) = hv;
                    __half2* mp = (__half2*)(g_hmax + (size_t)r * DD + c0);
                    if (firstLayer) {
                        *mp = hv;
                    } else {
                        *mp = __hmax2(*mp, hv);
                    }
                }
            }
        }
    }
}

// ---------------- final linear: hmax(fp16, Mx128) @ Wlin(fp32 128x64) + blin ----
__global__ __launch_bounds__(256) void final_gemm_kernel(
    const float* __restrict__ W, const float* __restrict__ b,
    float* __restrict__ out, int M)
{
    __shared__ __align__(16) float Ws[DD * OO];
    __shared__ __align__(16) float As[16][DD];

    int tid = threadIdx.x;
    for (int i = tid; i < DD * OO / 4; i += 256)
        ((float4*)Ws)[i] = ((const float4*)W)[i];

    int row0 = blockIdx.x * 16;
    for (int i = tid; i < 512; i += 256) {
        int r = i >> 5;
        int c4 = (i & 31) * 4;
        int gr = row0 + r;
        float4 v = make_float4(0.f, 0.f, 0.f, 0.f);
        if (gr < M) {
            uint2 u = *(const uint2*)(g_hmax + (size_t)gr * DD + c4);
            float2 f0 = __half22float2(*(__half2*)&u.x);
            float2 f1 = __half22float2(*(__half2*)&u.y);
            v = make_float4(f0.x, f0.y, f1.x, f1.y);
        }
        *(float4*)&As[r][c4] = v;
    }
    __syncthreads();

    int col = tid & 63;
    int rgrp = tid >> 6;
    float acc[4] = { 0.f, 0.f, 0.f, 0.f };
    #pragma unroll 4
    for (int k = 0; k < DD; k++) {
        float w = Ws[k * OO + col];
        #pragma unroll
        for (int i = 0; i < 4; i++)
            acc[i] += As[rgrp + i * 4][k] * w;
    }
    float bb = b[col];
    #pragma unroll
    for (int i = 0; i < 4; i++) {
        int r = row0 + rgrp + i * 4;
        if (r < M) out[(size_t)r * OO + col] = acc[i] + bb;
    }
}

// ---------------- launch ----------------
extern "C" void kernel_launch(void* const* d_in, const int* in_sizes, int n_in,
                              void* d_out, int out_size) {
    const float* x     = (const float*)d_in[0];
    const int*   ei    = (const int*)d_in[1];
    const float* Wself = (const float*)d_in[2];
    const float* bself = (const float*)d_in[3];
    const float* Wstd  = (const float*)d_in[4];
    const float* bstd  = (const float*)d_in[5];
    const float* Wdts  = (const float*)d_in[6];
    const float* bdts  = (const float*)d_in[7];
    const float* Wlin  = (const float*)d_in[8];
    const float* blin  = (const float*)d_in[9];
    const float* alpha = (const float*)d_in[10];

    int M = in_sizes[0] / DD;        // 50000
    int E = in_sizes[1] / 2;         // 800000

    __half* hx; cudaGetSymbolAddress((void**)&hx, g_hx);
    __half* h0; cudaGetSymbolAddress((void**)&h0, g_h0);
    __half* h1; cudaGetSymbolAddress((void**)&h1, g_h1);
    __half* wt; cudaGetSymbolAddress((void**)&wt, g_Wt);
    int* deg0p; cudaGetSymbolAddress((void**)&deg0p, g_deg0);
    int* deg1p; cudaGetSymbolAddress((void**)&deg1p, g_deg1);

    // zero degree arrays via memset nodes (not kernel launches)
    cudaMemsetAsync(deg0p, 0, M * sizeof(int));
    cudaMemsetAsync(deg1p, 0, M * sizeof(int));

    // CSR build + x conversion; launch index 3 = agg_kernel (for ncu)
    count_kernel<<<(E + 255) / 256, 256>>>(ei, E);          // idx 0
    scan_kernel<<<2, 1024>>>(M);                            // idx 1
    int total4 = M * DD / 4;
    int fillBlocks = (E + 255) / 256;
    int convBlocks = (total4 + 255) / 256;
    fill_convert_kernel<<<fillBlocks + convBlocks, 256>>>(  // idx 2
        ei, E, x, total4, fillBlocks);

    // layers
    const __half* cur = hx;
    __half* bufs[2] = { h0, h1 };
    int gemm_grid = (M + 127) / 128;
    int agg_grid = (M * 32 + 255) / 256;   // one warp per node
    for (int l = 0; l < LL; l++) {
        agg_kernel<<<agg_grid, 256>>>(cur, alpha, M);       // idx 3 (layer 0)
        if (l == 0)
            prep_weights_kernel<<<(LL * 3 * DD * DD + 255) / 256, 256>>>(Wself, Wstd, Wdts);
        __half* outb = bufs[l & 1];
        gemm_layer_f16<<<gemm_grid, 256>>>(
            cur,
            wt + (size_t)l * 3 * DD * DD,
            bself + (size_t)l * DD,
            bstd  + (size_t)l * DD,
            bdts  + (size_t)l * DD,
            alpha, outb, (l == 0) ? 1 : 0, M);
        cur = outb;
    }

    // final linear
    final_gemm_kernel<<<(M + 15) / 16, 256>>>(Wlin, blin, (float*)d_out, M);
}

// round 8
// speedup vs baseline: 1.0821x; 1.0228x over previous
#include <cuda_runtime.h>
#include <cuda_fp16.h>
#include <cuda_bf16.h>

#define NN 50000
#define EE 800000
#define DD 128
#define OO 64
#define LL 3

// ---------------- scratch (device globals) ----------------
__device__ __half g_hx[NN * DD];      // x converted to fp16
__device__ __half g_h0[NN * DD];
__device__ __half g_h1[NN * DD];
__device__ __half g_agg0[NN * DD];    // (1-a)/deg * sum_{src->dst}
__device__ __half g_agg1[NN * DD];    // a/deg * sum_{dst->src}
__device__ __half g_hmax[NN * DD];
__device__ __half g_Wt[LL * 3 * DD * DD];   // weights fp16, transposed [mat][n][k]

__device__ int g_deg0[NN];
__device__ int g_deg1[NN];
__device__ int g_rp0[NN + 1];
__device__ int g_rp1[NN + 1];
__device__ int g_cur0[NN];
__device__ int g_cur1[NN];
__device__ int g_col0[EE];            // CSR by dst, values = src
__device__ int g_col1[EE];            // CSR by src, values = dst

// ---------------- prep: transpose+convert weights ----------------
__global__ void prep_weights_kernel(const float* __restrict__ Wself,
                                    const float* __restrict__ Wstd,
                                    const float* __restrict__ Wdts) {
    int idx = blockIdx.x * blockDim.x + threadIdx.x;
    if (idx >= LL * 3 * DD * DD) return;
    int mat = idx >> 14;          // l*3+s
    int r = (idx >> 7) & 127;     // k (input dim)
    int c = idx & 127;            // n (output dim)
    int l = mat / 3, s = mat % 3;
    const float* W = (s == 0) ? Wself : (s == 1) ? Wstd : Wdts;
    float v = W[(size_t)l * DD * DD + r * DD + c];
    g_Wt[(size_t)mat * DD * DD + c * DD + r] = __float2half(v);
}

// ---------------- CSR build ----------------
__global__ void count_kernel(const int* __restrict__ ei, int E) {
    int e = blockIdx.x * blockDim.x + threadIdx.x;
    if (e >= E) return;
    int src = ei[e];
    int dst = ei[E + e];
    atomicAdd(&g_deg0[dst], 1);
    atomicAdd(&g_deg1[src], 1);
}

__global__ void scan_kernel(int n) {
    const int* deg = (blockIdx.x == 0) ? g_deg0 : g_deg1;
    int* rp = (blockIdx.x == 0) ? g_rp0 : g_rp1;
    int* cur = (blockIdx.x == 0) ? g_cur0 : g_cur1;

    __shared__ int sums[1024];
    int t = threadIdx.x;
    int chunk = (n + 1023) / 1024;
    int begin = t * chunk;
    int end = min(begin + chunk, n);
    int s = 0;
    for (int i = begin; i < end; i++) s += deg[i];
    sums[t] = s;
    __syncthreads();
    for (int off = 1; off < 1024; off <<= 1) {
        int v = (t >= off) ? sums[t - off] : 0;
        __syncthreads();
        sums[t] += v;
        __syncthreads();
    }
    int prefix = (t == 0) ? 0 : sums[t - 1];
    for (int i = begin; i < end; i++) {
        rp[i] = prefix;
        cur[i] = prefix;
        prefix += deg[i];
    }
    if (t == 1023) rp[n] = prefix;
}

// fused: blocks [0, fillBlocks) do CSR fill; rest convert x -> fp16
__global__ void fill_convert_kernel(const int* __restrict__ ei, int E,
                                    const float* __restrict__ x, int total4,
                                    int fillBlocks) {
    if ((int)blockIdx.x < fillBlocks) {
        int e = blockIdx.x * blockDim.x + threadIdx.x;
        if (e >= E) return;
        int src = ei[e];
        int dst = ei[E + e];
        int p0 = atomicAdd(&g_cur0[dst], 1);
        g_col0[p0] = src;
        int p1 = atomicAdd(&g_cur1[src], 1);
        g_col1[p1] = dst;
    } else {
        int i = (blockIdx.x - fillBlocks) * blockDim.x + threadIdx.x;
        if (i >= total4) return;
        float4 v = ((const float4*)x)[i];
        __half2 h0 = __floats2half2_rn(v.x, v.y);
        __half2 h1 = __floats2half2_rn(v.z, v.w);
        uint2 u;
        u.x = *(unsigned*)&h0;
        u.y = *(unsigned*)&h1;
        ((uint2*)g_hx)[i] = u;
    }
}

// ---------------- aggregation (fp16): one warp per node ----------------
// Inner 2 reduction levels in HADD2 (packed fp16), partial sums accumulated
// in fp32. Cuts issue-slot count per gathered element ~2x.
__device__ __forceinline__ __half2 u2h(unsigned u) { return *(__half2*)&u; }

__global__ void agg_kernel(const __half* __restrict__ h,
                           const float* __restrict__ alpha, int M) {
    int gw = (blockIdx.x * blockDim.x + threadIdx.x) >> 5;
    if (gw >= M) return;
    int lane = threadIdx.x & 31;
    int base = lane * 4;   // halves
    float a = alpha[0];

    #pragma unroll
    for (int dir = 0; dir < 2; dir++) {
        const int* rp  = dir ? g_rp1  : g_rp0;
        const int* col = dir ? g_col1 : g_col0;
        __half* out    = dir ? g_agg1 : g_agg0;
        float coef     = dir ? a : (1.f - a);

        int s = rp[gw], e = rp[gw + 1];
        float4 acc = make_float4(0.f, 0.f, 0.f, 0.f);
        int i = s;
        for (; i + 3 < e; i += 4) {
            int n0 = col[i],     n1 = col[i + 1];
            int n2 = col[i + 2], n3 = col[i + 3];
            uint2 u0 = *(const uint2*)(h + (size_t)n0 * DD + base);
            uint2 u1 = *(const uint2*)(h + (size_t)n1 * DD + base);
            uint2 u2 = *(const uint2*)(h + (size_t)n2 * DD + base);
            uint2 u3 = *(const uint2*)(h + (size_t)n3 * DD + base);
            // 2-level fp16 tree (same-sign values, <=2 roundings/element)
            __half2 s0 = __hadd2(__hadd2(u2h(u0.x), u2h(u1.x)),
                                 __hadd2(u2h(u2.x), u2h(u3.x)));
            __half2 s1 = __hadd2(__hadd2(u2h(u0.y), u2h(u1.y)),
                                 __hadd2(u2h(u2.y), u2h(u3.y)));
            float2 f0 = __half22float2(s0);
            float2 f1 = __half22float2(s1);
            acc.x += f0.x; acc.y += f0.y;
            acc.z += f1.x; acc.w += f1.y;
        }
        for (; i < e; i++) {
            int n0 = col[i];
            uint2 u0 = *(const uint2*)(h + (size_t)n0 * DD + base);
            float2 f0 = __half22float2(u2h(u0.x));
            float2 f1 = __half22float2(u2h(u0.y));
            acc.x += f0.x; acc.y += f0.y;
            acc.z += f1.x; acc.w += f1.y;
        }
        float sc = coef / fmaxf((float)(e - s), 1.f);
        __half2 o0 = __floats2half2_rn(acc.x * sc, acc.y * sc);
        __half2 o1 = __floats2half2_rn(acc.z * sc, acc.w * sc);
        uint2 u;
        u.x = *(unsigned*)&o0;
        u.y = *(unsigned*)&o1;
        *(uint2*)(out + (size_t)gw * DD + base) = u;
    }
}

// ---------------- fp16 tensor-core layer GEMM ----------------
// [h|agg0|agg1](Mx384 fp16) @ Wt(384x128 fp16, pre-transposed [n][k])
// 256 threads = 8 warps (4x2), warp tile 32x64, mma.m16n8k16.f16.f16.f32,
// BK=32, 12 chunks, double-buffered smem, 1 sync/chunk.
#define SA 40   // smem row stride in halves

__global__ __launch_bounds__(256) void gemm_layer_f16(
    const __half* __restrict__ A0,
    const __half* __restrict__ Wt,   // layer base (3 mats)
    const float* __restrict__ bs0,
    const float* __restrict__ bs1,
    const float* __restrict__ bs2,
    const float* __restrict__ alpha,
    __half* __restrict__ Hout,
    int firstLayer, int M)
{
    __shared__ __align__(16) __half As[2][128 * SA];
    __shared__ __align__(16) __half Bs[2][128 * SA];
    __shared__ float bias_s[DD];

    int tid = threadIdx.x;
    int block_row = blockIdx.x * 128;
    int warpId = tid >> 5;
    int lane = tid & 31;
    int g = lane >> 2;
    int t = lane & 3;
    int warp_row = warpId & 3;
    int warp_col = warpId >> 2;

    if (tid < DD) {
        float a = alpha[0];
        bias_s[tid] = bs0[tid] + (1.f - a) * bs1[tid] + a * bs2[tid];
    }

    float acc[2][8][4];
    #pragma unroll
    for (int mt = 0; mt < 2; mt++)
        #pragma unroll
        for (int nt = 0; nt < 8; nt++)
            #pragma unroll
            for (int r = 0; r < 4; r++) acc[mt][nt][r] = 0.f;

    const __half* Aseg[3] = { A0, g_agg0, g_agg1 };

    int l_row = tid >> 2;          // 0..63
    int l_kq = (tid & 3) * 8;      // halves: 0,8,16,24

    uint4 ra[2], rb[2];

    auto load_chunk = [&](int c) {
        int seg = c >> 2;
        int kl = (c & 3) * 32;
        const __half* A = Aseg[seg];
        const __half* B = Wt + (size_t)seg * DD * DD;
        #pragma unroll
        for (int j = 0; j < 2; j++) {
            int row = l_row + j * 64;
            int gr = block_row + row;
            ra[j] = (gr < M) ? *(const uint4*)(A + (size_t)gr * DD + kl + l_kq)
                             : make_uint4(0u, 0u, 0u, 0u);
            rb[j] = *(const uint4*)(B + (size_t)row * DD + kl + l_kq);
        }
    };
    auto store_chunk = [&](int buf) {
        #pragma unroll
        for (int j = 0; j < 2; j++) {
            int row = l_row + j * 64;
            *(uint4*)&As[buf][row * SA + l_kq] = ra[j];
            *(uint4*)&Bs[buf][row * SA + l_kq] = rb[j];
        }
    };

    load_chunk(0);
    store_chunk(0);
    __syncthreads();

    #pragma unroll 1
    for (int c = 0; c < 12; c++) {
        int buf = c & 1;
        if (c < 11) load_chunk(c + 1);

        #pragma unroll
        for (int ks = 0; ks < 2; ks++) {
            int k0 = ks * 16;
            unsigned af[2][4];
            #pragma unroll
            for (int mt = 0; mt < 2; mt++) {
                int mrow = warp_row * 32 + mt * 16;
                const __half* base = &As[buf][0];
                af[mt][0] = *(const unsigned*)&base[(mrow + g) * SA + k0 + 2 * t];
                af[mt][1] = *(const unsigned*)&base[(mrow + g + 8) * SA + k0 + 2 * t];
                af[mt][2] = *(const unsigned*)&base[(mrow + g) * SA + k0 + 8 + 2 * t];
                af[mt][3] = *(const unsigned*)&base[(mrow + g + 8) * SA + k0 + 8 + 2 * t];
            }
            unsigned bf[8][2];
            #pragma unroll
            for (int nt = 0; nt < 8; nt++) {
                int n = warp_col * 64 + nt * 8 + g;
                const __half* base = &Bs[buf][0];
                bf[nt][0] = *(const unsigned*)&base[n * SA + k0 + 2 * t];
                bf[nt][1] = *(const unsigned*)&base[n * SA + k0 + 8 + 2 * t];
            }
            #pragma unroll
            for (int mt = 0; mt < 2; mt++)
                #pragma unroll
                for (int nt = 0; nt < 8; nt++) {
                    asm volatile(
                        "mma.sync.aligned.m16n8k16.row.col.f32.f16.f16.f32 "
                        "{%0,%1,%2,%3}, {%4,%5,%6,%7}, {%8,%9}, {%0,%1,%2,%3};"
                        : "+f"(acc[mt][nt][0]), "+f"(acc[mt][nt][1]),
                          "+f"(acc[mt][nt][2]), "+f"(acc[mt][nt][3])
                        : "r"(af[mt][0]), "r"(af[mt][1]), "r"(af[mt][2]), "r"(af[mt][3]),
                          "r"(bf[nt][0]), "r"(bf[nt][1]));
                }
        }
        if (c < 11) {
            store_chunk(buf ^ 1);
            __syncthreads();
        }
    }

    // epilogue: bias + relu + store h(fp16) + JK max(fp16)
    #pragma unroll
    for (int mt = 0; mt < 2; mt++) {
        #pragma unroll
        for (int nt = 0; nt < 8; nt++) {
            int c0 = warp_col * 64 + nt * 8 + 2 * t;
            float b0v = bias_s[c0];
            float b1v = bias_s[c0 + 1];
            #pragma unroll
            for (int rr = 0; rr < 2; rr++) {
                int r = block_row + warp_row * 32 + mt * 16 + g + rr * 8;
                if (r < M) {
                    float v0 = fmaxf(acc[mt][nt][rr * 2 + 0] + b0v, 0.f);
                    float v1 = fmaxf(acc[mt][nt][rr * 2 + 1] + b1v, 0.f);
                    __half2 hv = __floats2half2_rn(v0, v1);
                    *(__half2*)(Hout + (size_t)r * DD + c0) = hv;
                    __half2* mp = (__half2*)(g_hmax + (size_t)r * DD + c0);
                    if (firstLayer) {
                        *mp = hv;
                    } else {
                        *mp = __hmax2(*mp, hv);
                    }
                }
            }
        }
    }
}

// ---------------- final linear: hmax(fp16, Mx128) @ Wlin(fp32 128x64) + blin ----
__global__ __launch_bounds__(256) void final_gemm_kernel(
    const float* __restrict__ W, const float* __restrict__ b,
    float* __restrict__ out, int M)
{
    __shared__ __align__(16) float Ws[DD * OO];
    __shared__ __align__(16) float As[16][DD];

    int tid = threadIdx.x;
    for (int i = tid; i < DD * OO / 4; i += 256)
        ((float4*)Ws)[i] = ((const float4*)W)[i];

    int row0 = blockIdx.x * 16;
    for (int i = tid; i < 512; i += 256) {
        int r = i >> 5;
        int c4 = (i & 31) * 4;
        int gr = row0 + r;
        float4 v = make_float4(0.f, 0.f, 0.f, 0.f);
        if (gr < M) {
            uint2 u = *(const uint2*)(g_hmax + (size_t)gr * DD + c4);
            float2 f0 = __half22float2(*(__half2*)&u.x);
            float2 f1 = __half22float2(*(__half2*)&u.y);
            v = make_float4(f0.x, f0.y, f1.x, f1.y);
        }
        *(float4*)&As[r][c4] = v;
    }
    __syncthreads();

    int col = tid & 63;
    int rgrp = tid >> 6;
    float acc[4] = { 0.f, 0.f, 0.f, 0.f };
    #pragma unroll 4
    for (int k = 0; k < DD; k++) {
        float w = Ws[k * OO + col];
        #pragma unroll
        for (int i = 0; i < 4; i++)
            acc[i] += As[rgrp + i * 4][k] * w;
    }
    float bb = b[col];
    #pragma unroll
    for (int i = 0; i < 4; i++) {
        int r = row0 + rgrp + i * 4;
        if (r < M) out[(size_t)r * OO + col] = acc[i] + bb;
    }
}

// ---------------- launch ----------------
extern "C" void kernel_launch(void* const* d_in, const int* in_sizes, int n_in,
                              void* d_out, int out_size) {
    const float* x     = (const float*)d_in[0];
    const int*   ei    = (const int*)d_in[1];
    const float* Wself = (const float*)d_in[2];
    const float* bself = (const float*)d_in[3];
    const float* Wstd  = (const float*)d_in[4];
    const float* bstd  = (const float*)d_in[5];
    const float* Wdts  = (const float*)d_in[6];
    const float* bdts  = (const float*)d_in[7];
    const float* Wlin  = (const float*)d_in[8];
    const float* blin  = (const float*)d_in[9];
    const float* alpha = (const float*)d_in[10];

    int M = in_sizes[0] / DD;        // 50000
    int E = in_sizes[1] / 2;         // 800000

    __half* hx; cudaGetSymbolAddress((void**)&hx, g_hx);
    __half* h0; cudaGetSymbolAddress((void**)&h0, g_h0);
    __half* h1; cudaGetSymbolAddress((void**)&h1, g_h1);
    __half* wt; cudaGetSymbolAddress((void**)&wt, g_Wt);
    int* deg0p; cudaGetSymbolAddress((void**)&deg0p, g_deg0);
    int* deg1p; cudaGetSymbolAddress((void**)&deg1p, g_deg1);

    // zero degree arrays via memset nodes (not kernel launches)
    cudaMemsetAsync(deg0p, 0, M * sizeof(int));
    cudaMemsetAsync(deg1p, 0, M * sizeof(int));

    // CSR build + x conversion; launch index 3 = agg_kernel (for ncu)
    count_kernel<<<(E + 255) / 256, 256>>>(ei, E);          // idx 0
    scan_kernel<<<2, 1024>>>(M);                            // idx 1
    int total4 = M * DD / 4;
    int fillBlocks = (E + 255) / 256;
    int convBlocks = (total4 + 255) / 256;
    fill_convert_kernel<<<fillBlocks + convBlocks, 256>>>(  // idx 2
        ei, E, x, total4, fillBlocks);

    // layers
    const __half* cur = hx;
    __half* bufs[2] = { h0, h1 };
    int gemm_grid = (M + 127) / 128;
    int agg_grid = (M * 32 + 255) / 256;   // one warp per node
    for (int l = 0; l < LL; l++) {
        agg_kernel<<<agg_grid, 256>>>(cur, alpha, M);       // idx 3 (layer 0)
        if (l == 0)
            prep_weights_kernel<<<(LL * 3 * DD * DD + 255) / 256, 256>>>(Wself, Wstd, Wdts);
        __half* outb = bufs[l & 1];
        gemm_layer_f16<<<gemm_grid, 256>>>(
            cur,
            wt + (size_t)l * 3 * DD * DD,
            bself + (size_t)l * DD,
            bstd  + (size_t)l * DD,
            bdts  + (size_t)l * DD,
            alpha, outb, (l == 0) ? 1 : 0, M);
        cur = outb;
    }

    // final linear
    final_gemm_kernel<<<(M + 15) / 16, 256>>>(Wlin, blin, (float*)d_out, M);
}

// round 9
// speedup vs baseline: 1.1805x; 1.0910x over previous
#include <cuda_runtime.h>
#include <cuda_fp16.h>
#include <cuda_bf16.h>

#define NN 50000
#define EE 800000
#define DD 128
#define OO 64
#define LL 3

// ---------------- scratch (device globals) ----------------
__device__ __half g_hx[NN * DD];      // x converted to fp16
__device__ __half g_h0[NN * DD];
__device__ __half g_h1[NN * DD];
__device__ __half g_agg0[NN * DD];    // (1-a)/deg * sum_{src->dst}
__device__ __half g_agg1[NN * DD];    // a/deg * sum_{dst->src}
__device__ __half g_hmax[NN * DD];
__device__ __half g_Wt[LL * 3 * DD * DD];   // layer weights fp16, [mat][n][k]
__device__ __half g_Wlt[OO * DD];           // Wlin fp16, [n][k]

__device__ int g_deg[2 * NN];         // [0]=by dst, [1]=by src
__device__ int g_rp0[NN + 1];
__device__ int g_rp1[NN + 1];
__device__ int g_cur0[NN];
__device__ int g_cur1[NN];
__device__ int g_col0[EE];            // CSR by dst, values = src
__device__ int g_col1[EE];            // CSR by src, values = dst

// ---------------- cp.async helper ----------------
__device__ __forceinline__ void cp16(__half* s, const void* g, bool v) {
    unsigned sa = (unsigned)__cvta_generic_to_shared(s);
    int sz = v ? 16 : 0;
    asm volatile("cp.async.ca.shared.global [%0], [%1], 16, %2;"
                 :: "r"(sa), "l"(g), "r"(sz));
}

// ---------------- CSR build ----------------
__global__ void count_kernel(const int* __restrict__ ei, int E) {
    int e = blockIdx.x * blockDim.x + threadIdx.x;
    if (e >= E) return;
    int src = ei[e];
    int dst = ei[E + e];
    atomicAdd(&g_deg[dst], 1);
    atomicAdd(&g_deg[NN + src], 1);
}

__global__ void scan_kernel(int n) {
    const int* deg = g_deg + blockIdx.x * NN;
    int* rp = (blockIdx.x == 0) ? g_rp0 : g_rp1;
    int* cur = (blockIdx.x == 0) ? g_cur0 : g_cur1;

    __shared__ int sums[1024];
    int t = threadIdx.x;
    int chunk = (n + 1023) / 1024;
    int begin = t * chunk;
    int end = min(begin + chunk, n);
    int s = 0;
    for (int i = begin; i < end; i++) s += deg[i];
    sums[t] = s;
    __syncthreads();
    for (int off = 1; off < 1024; off <<= 1) {
        int v = (t >= off) ? sums[t - off] : 0;
        __syncthreads();
        sums[t] += v;
        __syncthreads();
    }
    int prefix = (t == 0) ? 0 : sums[t - 1];
    for (int i = begin; i < end; i++) {
        rp[i] = prefix;
        cur[i] = prefix;
        prefix += deg[i];
    }
    if (t == 1023) rp[n] = prefix;
}

// fused: CSR fill | x->fp16 convert | weight transpose+convert
__global__ void fill_convert_prep_kernel(
    const int* __restrict__ ei, int E,
    const float* __restrict__ x, int total4,
    const float* __restrict__ Wself, const float* __restrict__ Wstd,
    const float* __restrict__ Wdts, const float* __restrict__ Wlin,
    int fillBlocks, int convBlocks)
{
    int b = blockIdx.x;
    if (b < fillBlocks) {
        int e = b * blockDim.x + threadIdx.x;
        if (e >= E) return;
        int src = ei[e];
        int dst = ei[E + e];
        int p0 = atomicAdd(&g_cur0[dst], 1);
        g_col0[p0] = src;
        int p1 = atomicAdd(&g_cur1[src], 1);
        g_col1[p1] = dst;
    } else if (b < fillBlocks + convBlocks) {
        int i = (b - fillBlocks) * blockDim.x + threadIdx.x;
        if (i >= total4) return;
        float4 v = ((const float4*)x)[i];
        __half2 h0 = __floats2half2_rn(v.x, v.y);
        __half2 h1 = __floats2half2_rn(v.z, v.w);
        uint2 u;
        u.x = *(unsigned*)&h0;
        u.y = *(unsigned*)&h1;
        ((uint2*)g_hx)[i] = u;
    } else {
        int idx = (b - fillBlocks - convBlocks) * blockDim.x + threadIdx.x;
        if (idx < LL * 3 * DD * DD) {
            int mat = idx >> 14;
            int r = (idx >> 7) & 127;
            int c = idx & 127;
            int l = mat / 3, s = mat % 3;
            const float* W = (s == 0) ? Wself : (s == 1) ? Wstd : Wdts;
            float v = W[(size_t)l * DD * DD + r * DD + c];
            g_Wt[(size_t)mat * DD * DD + c * DD + r] = __float2half(v);
        } else {
            int i2 = idx - LL * 3 * DD * DD;
            if (i2 < OO * DD) {
                int n = i2 >> 7;
                int k = i2 & 127;
                g_Wlt[n * DD + k] = __float2half(Wlin[k * OO + n]);
            }
        }
    }
}

// ---------------- aggregation: one warp per node, 8-deep fp16 tree ---------
__device__ __forceinline__ __half2 u2h(unsigned u) { return *(__half2*)&u; }

__global__ void agg_kernel(const __half* __restrict__ h,
                           const float* __restrict__ alpha, int M) {
    int gw = (blockIdx.x * blockDim.x + threadIdx.x) >> 5;
    if (gw >= M) return;
    int lane = threadIdx.x & 31;
    int base = lane * 4;   // halves
    float a = alpha[0];

    #pragma unroll
    for (int dir = 0; dir < 2; dir++) {
        const int* rp  = dir ? g_rp1  : g_rp0;
        const int* col = dir ? g_col1 : g_col0;
        __half* out    = dir ? g_agg1 : g_agg0;
        float coef     = dir ? a : (1.f - a);

        int s = rp[gw], e = rp[gw + 1];
        float4 acc = make_float4(0.f, 0.f, 0.f, 0.f);
        int i = s;
        for (; i + 7 < e; i += 8) {
            uint2 u0 = *(const uint2*)(h + (size_t)col[i]     * DD + base);
            uint2 u1 = *(const uint2*)(h + (size_t)col[i + 1] * DD + base);
            uint2 u2 = *(const uint2*)(h + (size_t)col[i + 2] * DD + base);
            uint2 u3 = *(const uint2*)(h + (size_t)col[i + 3] * DD + base);
            uint2 u4 = *(const uint2*)(h + (size_t)col[i + 4] * DD + base);
            uint2 u5 = *(const uint2*)(h + (size_t)col[i + 5] * DD + base);
            uint2 u6 = *(const uint2*)(h + (size_t)col[i + 6] * DD + base);
            uint2 u7 = *(const uint2*)(h + (size_t)col[i + 7] * DD + base);
            __half2 s0 = __hadd2(
                __hadd2(__hadd2(u2h(u0.x), u2h(u1.x)), __hadd2(u2h(u2.x), u2h(u3.x))),
                __hadd2(__hadd2(u2h(u4.x), u2h(u5.x)), __hadd2(u2h(u6.x), u2h(u7.x))));
            __half2 s1 = __hadd2(
                __hadd2(__hadd2(u2h(u0.y), u2h(u1.y)), __hadd2(u2h(u2.y), u2h(u3.y))),
                __hadd2(__hadd2(u2h(u4.y), u2h(u5.y)), __hadd2(u2h(u6.y), u2h(u7.y))));
            float2 f0 = __half22float2(s0);
            float2 f1 = __half22float2(s1);
            acc.x += f0.x; acc.y += f0.y;
            acc.z += f1.x; acc.w += f1.y;
        }
        for (; i + 3 < e; i += 4) {
            uint2 u0 = *(const uint2*)(h + (size_t)col[i]     * DD + base);
            uint2 u1 = *(const uint2*)(h + (size_t)col[i + 1] * DD + base);
            uint2 u2 = *(const uint2*)(h + (size_t)col[i + 2] * DD + base);
            uint2 u3 = *(const uint2*)(h + (size_t)col[i + 3] * DD + base);
            __half2 s0 = __hadd2(__hadd2(u2h(u0.x), u2h(u1.x)),
                                 __hadd2(u2h(u2.x), u2h(u3.x)));
            __half2 s1 = __hadd2(__hadd2(u2h(u0.y), u2h(u1.y)),
                                 __hadd2(u2h(u2.y), u2h(u3.y)));
            float2 f0 = __half22float2(s0);
            float2 f1 = __half22float2(s1);
            acc.x += f0.x; acc.y += f0.y;
            acc.z += f1.x; acc.w += f1.y;
        }
        for (; i < e; i++) {
            uint2 u0 = *(const uint2*)(h + (size_t)col[i] * DD + base);
            float2 f0 = __half22float2(u2h(u0.x));
            float2 f1 = __half22float2(u2h(u0.y));
            acc.x += f0.x; acc.y += f0.y;
            acc.z += f1.x; acc.w += f1.y;
        }
        float sc = coef / fmaxf((float)(e - s), 1.f);
        __half2 o0 = __floats2half2_rn(acc.x * sc, acc.y * sc);
        __half2 o1 = __floats2half2_rn(acc.z * sc, acc.w * sc);
        uint2 u;
        u.x = *(unsigned*)&o0;
        u.y = *(unsigned*)&o1;
        *(uint2*)(out + (size_t)gw * DD + base) = u;
    }
}

// ---------------- fp16 tensor-core layer GEMM (cp.async double buffer) -----
#define SA 40   // smem row stride in halves

__global__ __launch_bounds__(256) void gemm_layer_f16(
    const __half* __restrict__ A0,
    const __half* __restrict__ Wt,   // layer base (3 mats)
    const float* __restrict__ bs0,
    const float* __restrict__ bs1,
    const float* __restrict__ bs2,
    const float* __restrict__ alpha,
    __half* __restrict__ Hout,
    int firstLayer, int M)
{
    __shared__ __align__(16) __half As[2][128 * SA];
    __shared__ __align__(16) __half Bs[2][128 * SA];
    __shared__ float bias_s[DD];

    int tid = threadIdx.x;
    int block_row = blockIdx.x * 128;
    int warpId = tid >> 5;
    int lane = tid & 31;
    int g = lane >> 2;
    int t = lane & 3;
    int warp_row = warpId & 3;
    int warp_col = warpId >> 2;

    if (tid < DD) {
        float a = alpha[0];
        bias_s[tid] = bs0[tid] + (1.f - a) * bs1[tid] + a * bs2[tid];
    }

    float acc[2][8][4];
    #pragma unroll
    for (int mt = 0; mt < 2; mt++)
        #pragma unroll
        for (int nt = 0; nt < 8; nt++)
            #pragma unroll
            for (int r = 0; r < 4; r++) acc[mt][nt][r] = 0.f;

    const __half* Aseg[3] = { A0, g_agg0, g_agg1 };

    int l_row = tid >> 2;          // 0..63
    int l_kq = (tid & 3) * 8;      // halves: 0,8,16,24

    auto cp_chunk = [&](int c, int buf) {
        int seg = c >> 2;
        int kl = (c & 3) * 32;
        const __half* A = Aseg[seg];
        const __half* B = Wt + (size_t)seg * DD * DD;
        #pragma unroll
        for (int j = 0; j < 2; j++) {
            int row = l_row + j * 64;
            int gr = block_row + row;
            cp16(&As[buf][row * SA + l_kq], A + (size_t)gr * DD + kl + l_kq, gr < M);
            cp16(&Bs[buf][row * SA + l_kq], B + (size_t)row * DD + kl + l_kq, true);
        }
        asm volatile("cp.async.commit_group;");
    };

    cp_chunk(0, 0);

    #pragma unroll 1
    for (int c = 0; c < 12; c++) {
        int buf = c & 1;
        if (c < 11) {
            cp_chunk(c + 1, buf ^ 1);
            asm volatile("cp.async.wait_group 1;");
        } else {
            asm volatile("cp.async.wait_group 0;");
        }
        __syncthreads();

        #pragma unroll
        for (int ks = 0; ks < 2; ks++) {
            int k0 = ks * 16;
            unsigned af[2][4];
            #pragma unroll
            for (int mt = 0; mt < 2; mt++) {
                int mrow = warp_row * 32 + mt * 16;
                const __half* base = &As[buf][0];
                af[mt][0] = *(const unsigned*)&base[(mrow + g) * SA + k0 + 2 * t];
                af[mt][1] = *(const unsigned*)&base[(mrow + g + 8) * SA + k0 + 2 * t];
                af[mt][2] = *(const unsigned*)&base[(mrow + g) * SA + k0 + 8 + 2 * t];
                af[mt][3] = *(const unsigned*)&base[(mrow + g + 8) * SA + k0 + 8 + 2 * t];
            }
            unsigned bf[8][2];
            #pragma unroll
            for (int nt = 0; nt < 8; nt++) {
                int n = warp_col * 64 + nt * 8 + g;
                const __half* base = &Bs[buf][0];
                bf[nt][0] = *(const unsigned*)&base[n * SA + k0 + 2 * t];
                bf[nt][1] = *(const unsigned*)&base[n * SA + k0 + 8 + 2 * t];
            }
            #pragma unroll
            for (int mt = 0; mt < 2; mt++)
                #pragma unroll
                for (int nt = 0; nt < 8; nt++) {
                    asm volatile(
                        "mma.sync.aligned.m16n8k16.row.col.f32.f16.f16.f32 "
                        "{%0,%1,%2,%3}, {%4,%5,%6,%7}, {%8,%9}, {%0,%1,%2,%3};"
                        : "+f"(acc[mt][nt][0]), "+f"(acc[mt][nt][1]),
                          "+f"(acc[mt][nt][2]), "+f"(acc[mt][nt][3])
                        : "r"(af[mt][0]), "r"(af[mt][1]), "r"(af[mt][2]), "r"(af[mt][3]),
                          "r"(bf[nt][0]), "r"(bf[nt][1]));
                }
        }
        __syncthreads();
    }

    // epilogue: bias + relu + store h(fp16) + JK max(fp16)
    #pragma unroll
    for (int mt = 0; mt < 2; mt++) {
        #pragma unroll
        for (int nt = 0; nt < 8; nt++) {
            int c0 = warp_col * 64 + nt * 8 + 2 * t;
            float b0v = bias_s[c0];
            float b1v = bias_s[c0 + 1];
            #pragma unroll
            for (int rr = 0; rr < 2; rr++) {
                int r = block_row + warp_row * 32 + mt * 16 + g + rr * 8;
                if (r < M) {
                    float v0 = fmaxf(acc[mt][nt][rr * 2 + 0] + b0v, 0.f);
                    float v1 = fmaxf(acc[mt][nt][rr * 2 + 1] + b1v, 0.f);
                    __half2 hv = __floats2half2_rn(v0, v1);
                    *(__half2*)(Hout + (size_t)r * DD + c0) = hv;
                    __half2* mp = (__half2*)(g_hmax + (size_t)r * DD + c0);
                    if (firstLayer) {
                        *mp = hv;
                    } else {
                        *mp = __hmax2(*mp, hv);
                    }
                }
            }
        }
    }
}

// ---------------- final linear via fp16 MMA: hmax @ Wlt^T + blin ------------
#define SF 136   // smem stride (halves), conflict-free

__global__ __launch_bounds__(256) void final_mma_kernel(
    const float* __restrict__ blin, float* __restrict__ out, int M)
{
    extern __shared__ char dynsm[];
    float* bias_s = (float*)dynsm;                      // 256B
    __half* As = (__half*)(dynsm + 256);                // 128*136*2
    __half* Bs = As + 128 * SF;                         // 64*136*2

    int tid = threadIdx.x;
    int block_row = blockIdx.x * 128;
    int warpId = tid >> 5;
    int lane = tid & 31;
    int g = lane >> 2;
    int t = lane & 3;
    int warp_row = warpId & 3;   // 32 rows
    int warp_col = warpId >> 2;  // 32 cols

    if (tid < OO) bias_s[tid] = blin[tid];

    // load A (hmax rows) 128x128 halves: 2048 uint4, 8 per thread
    #pragma unroll
    for (int k = 0; k < 8; k++) {
        int idx = tid + k * 256;
        int row = idx >> 4;
        int q = (idx & 15) * 8;
        int gr = block_row + row;
        uint4 v = make_uint4(0u, 0u, 0u, 0u);
        if (gr < M) v = *(const uint4*)(g_hmax + (size_t)gr * DD + q);
        *(uint4*)&As[row * SF + q] = v;
    }
    // load B (Wlt [n][k]) 64x128 halves: 1024 uint4, 4 per thread
    #pragma unroll
    for (int k = 0; k < 4; k++) {
        int idx = tid + k * 256;
        int row = idx >> 4;
        int q = (idx & 15) * 8;
        *(uint4*)&Bs[row * SF + q] = *(const uint4*)(g_Wlt + row * DD + q);
    }
    __syncthreads();

    float acc[2][4][4];
    #pragma unroll
    for (int mt = 0; mt < 2; mt++)
        #pragma unroll
        for (int nt = 0; nt < 4; nt++)
            #pragma unroll
            for (int r = 0; r < 4; r++) acc[mt][nt][r] = 0.f;

    #pragma unroll
    for (int kc = 0; kc < 8; kc++) {
        int k0 = kc * 16;
        unsigned af[2][4];
        #pragma unroll
        for (int mt = 0; mt < 2; mt++) {
            int mrow = warp_row * 32 + mt * 16;
            af[mt][0] = *(const unsigned*)&As[(mrow + g) * SF + k0 + 2 * t];
            af[mt][1] = *(const unsigned*)&As[(mrow + g + 8) * SF + k0 + 2 * t];
            af[mt][2] = *(const unsigned*)&As[(mrow + g) * SF + k0 + 8 + 2 * t];
            af[mt][3] = *(const unsigned*)&As[(mrow + g + 8) * SF + k0 + 8 + 2 * t];
        }
        unsigned bf[4][2];
        #pragma unroll
        for (int nt = 0; nt < 4; nt++) {
            int n = warp_col * 32 + nt * 8 + g;
            bf[nt][0] = *(const unsigned*)&Bs[n * SF + k0 + 2 * t];
            bf[nt][1] = *(const unsigned*)&Bs[n * SF + k0 + 8 + 2 * t];
        }
        #pragma unroll
        for (int mt = 0; mt < 2; mt++)
            #pragma unroll
            for (int nt = 0; nt < 4; nt++) {
                asm volatile(
                    "mma.sync.aligned.m16n8k16.row.col.f32.f16.f16.f32 "
                    "{%0,%1,%2,%3}, {%4,%5,%6,%7}, {%8,%9}, {%0,%1,%2,%3};"
                    : "+f"(acc[mt][nt][0]), "+f"(acc[mt][nt][1]),
                      "+f"(acc[mt][nt][2]), "+f"(acc[mt][nt][3])
                    : "r"(af[mt][0]), "r"(af[mt][1]), "r"(af[mt][2]), "r"(af[mt][3]),
                      "r"(bf[nt][0]), "r"(bf[nt][1]));
            }
    }

    #pragma unroll
    for (int mt = 0; mt < 2; mt++) {
        #pragma unroll
        for (int nt = 0; nt < 4; nt++) {
            int c0 = warp_col * 32 + nt * 8 + 2 * t;
            float b0v = bias_s[c0];
            float b1v = bias_s[c0 + 1];
            #pragma unroll
            for (int rr = 0; rr < 2; rr++) {
                int r = block_row + warp_row * 32 + mt * 16 + g + rr * 8;
                if (r < M) {
                    float2 o;
                    o.x = acc[mt][nt][rr * 2 + 0] + b0v;
                    o.y = acc[mt][nt][rr * 2 + 1] + b1v;
                    *(float2*)(out + (size_t)r * OO + c0) = o;
                }
            }
        }
    }
}

// ---------------- launch ----------------
extern "C" void kernel_launch(void* const* d_in, const int* in_sizes, int n_in,
                              void* d_out, int out_size) {
    const float* x     = (const float*)d_in[0];
    const int*   ei    = (const int*)d_in[1];
    const float* Wself = (const float*)d_in[2];
    const float* bself = (const float*)d_in[3];
    const float* Wstd  = (const float*)d_in[4];
    const float* bstd  = (const float*)d_in[5];
    const float* Wdts  = (const float*)d_in[6];
    const float* bdts  = (const float*)d_in[7];
    const float* Wlin  = (const float*)d_in[8];
    const float* blin  = (const float*)d_in[9];
    const float* alpha = (const float*)d_in[10];

    int M = in_sizes[0] / DD;        // 50000
    int E = in_sizes[1] / 2;         // 800000

    __half* hx; cudaGetSymbolAddress((void**)&hx, g_hx);
    __half* h0; cudaGetSymbolAddress((void**)&h0, g_h0);
    __half* h1; cudaGetSymbolAddress((void**)&h1, g_h1);
    __half* wt; cudaGetSymbolAddress((void**)&wt, g_Wt);
    int* degp; cudaGetSymbolAddress((void**)&degp, g_deg);

    const int FINAL_SMEM = 256 + (128 * SF + 64 * SF) * 2;   // 52480
    cudaFuncSetAttribute(final_mma_kernel,
                         cudaFuncAttributeMaxDynamicSharedMemorySize, FINAL_SMEM);

    // one memset node for both degree arrays
    cudaMemsetAsync(degp, 0, 2 * NN * sizeof(int));           // launch 0

    count_kernel<<<(E + 255) / 256, 256>>>(ei, E);            // 1
    scan_kernel<<<2, 1024>>>(M);                              // 2
    int total4 = M * DD / 4;
    int fillBlocks = (E + 255) / 256;
    int convBlocks = (total4 + 255) / 256;
    int prepBlocks = (LL * 3 * DD * DD + OO * DD + 255) / 256;
    fill_convert_prep_kernel<<<fillBlocks + convBlocks + prepBlocks, 256>>>(
        ei, E, x, total4, Wself, Wstd, Wdts, Wlin, fillBlocks, convBlocks);  // 3

    // layers
    const __half* cur = hx;
    __half* bufs[2] = { h0, h1 };
    int gemm_grid = (M + 127) / 128;
    int agg_grid = (M * 32 + 255) / 256;
    for (int l = 0; l < LL; l++) {
        agg_kernel<<<agg_grid, 256>>>(cur, alpha, M);         // 4 (layer 0)
        __half* outb = bufs[l & 1];
        gemm_layer_f16<<<gemm_grid, 256>>>(                   // 5 (layer 0) <- ncu
            cur,
            wt + (size_t)l * 3 * DD * DD,
            bself + (size_t)l * DD,
            bstd  + (size_t)l * DD,
            bdts  + (size_t)l * DD,
            alpha, outb, (l == 0) ? 1 : 0, M);
        cur = outb;
    }

    // final linear (fp16 MMA)
    final_mma_kernel<<<(M + 127) / 128, 256, FINAL_SMEM>>>(blin, (float*)d_out, M);
}

// round 10
// speedup vs baseline: 1.2031x; 1.0191x over previous
#include <cuda_runtime.h>
#include <cuda_fp16.h>
#include <cuda_bf16.h>

#define NN 50000
#define EE 800000
#define DD 128
#define OO 64
#define LL 3

// ---------------- scratch (device globals) ----------------
__device__ __half g_hx[NN * DD];      // x converted to fp16
__device__ __half g_h0[NN * DD];
__device__ __half g_h1[NN * DD];
__device__ __half g_agg0[NN * DD];    // (1-a)/deg * sum_{src->dst}
__device__ __half g_agg1[NN * DD];    // a/deg * sum_{dst->src}
__device__ __half g_hmax[NN * DD];
__device__ __half g_Wt[LL * 3 * DD * DD];   // layer weights fp16, [mat][n][k]
__device__ __half g_Wlt[OO * DD];           // Wlin fp16, [n][k]

__device__ int g_deg[2 * NN];         // [0]=by dst, [1]=by src
__device__ int g_rp0[NN + 1];
__device__ int g_rp1[NN + 1];
__device__ int g_cur0[NN];
__device__ int g_cur1[NN];
__device__ int g_col0[EE];            // CSR by dst, values = src
__device__ int g_col1[EE];            // CSR by src, values = dst

// ---------------- cp.async helper ----------------
__device__ __forceinline__ void cp16(__half* s, const void* g, bool v) {
    unsigned sa = (unsigned)__cvta_generic_to_shared(s);
    int sz = v ? 16 : 0;
    asm volatile("cp.async.ca.shared.global [%0], [%1], 16, %2;"
                 :: "r"(sa), "l"(g), "r"(sz));
}

// ---------------- CSR build ----------------
__global__ void count_kernel(const int* __restrict__ ei, int E) {
    int e = blockIdx.x * blockDim.x + threadIdx.x;
    if (e >= E) return;
    int src = ei[e];
    int dst = ei[E + e];
    atomicAdd(&g_deg[dst], 1);
    atomicAdd(&g_deg[NN + src], 1);
}

__global__ void scan_kernel(int n) {
    const int* deg = g_deg + blockIdx.x * NN;
    int* rp = (blockIdx.x == 0) ? g_rp0 : g_rp1;
    int* cur = (blockIdx.x == 0) ? g_cur0 : g_cur1;

    __shared__ int sums[1024];
    int t = threadIdx.x;
    int chunk = (n + 1023) / 1024;
    int begin = t * chunk;
    int end = min(begin + chunk, n);
    int s = 0;
    for (int i = begin; i < end; i++) s += deg[i];
    sums[t] = s;
    __syncthreads();
    for (int off = 1; off < 1024; off <<= 1) {
        int v = (t >= off) ? sums[t - off] : 0;
        __syncthreads();
        sums[t] += v;
        __syncthreads();
    }
    int prefix = (t == 0) ? 0 : sums[t - 1];
    for (int i = begin; i < end; i++) {
        rp[i] = prefix;
        cur[i] = prefix;
        prefix += deg[i];
    }
    if (t == 1023) rp[n] = prefix;
}

// fused: CSR fill | weight transpose+convert
__global__ void fill_prep_kernel(
    const int* __restrict__ ei, int E,
    const float* __restrict__ Wself, const float* __restrict__ Wstd,
    const float* __restrict__ Wdts, const float* __restrict__ Wlin,
    int fillBlocks)
{
    int b = blockIdx.x;
    if (b < fillBlocks) {
        int e = b * blockDim.x + threadIdx.x;
        if (e >= E) return;
        int src = ei[e];
        int dst = ei[E + e];
        int p0 = atomicAdd(&g_cur0[dst], 1);
        g_col0[p0] = src;
        int p1 = atomicAdd(&g_cur1[src], 1);
        g_col1[p1] = dst;
    } else {
        int idx = (b - fillBlocks) * blockDim.x + threadIdx.x;
        if (idx < LL * 3 * DD * DD) {
            int mat = idx >> 14;
            int r = (idx >> 7) & 127;
            int c = idx & 127;
            int l = mat / 3, s = mat % 3;
            const float* W = (s == 0) ? Wself : (s == 1) ? Wstd : Wdts;
            float v = W[(size_t)l * DD * DD + r * DD + c];
            g_Wt[(size_t)mat * DD * DD + c * DD + r] = __float2half(v);
        } else {
            int i2 = idx - LL * 3 * DD * DD;
            if (i2 < OO * DD) {
                int n = i2 >> 7;
                int k = i2 & 127;
                g_Wlt[n * DD + k] = __float2half(Wlin[k * OO + n]);
            }
        }
    }
}

__global__ void convert_x_kernel(const float* __restrict__ x, int total4) {
    int i = blockIdx.x * blockDim.x + threadIdx.x;
    if (i >= total4) return;
    float4 v = ((const float4*)x)[i];
    __half2 h0 = __floats2half2_rn(v.x, v.y);
    __half2 h1 = __floats2half2_rn(v.z, v.w);
    uint2 u;
    u.x = *(unsigned*)&h0;
    u.y = *(unsigned*)&h1;
    ((uint2*)g_hx)[i] = u;
}

// ---------------- aggregation: one warp per node, 4-deep fp16 tree ---------
__device__ __forceinline__ __half2 u2h(unsigned u) { return *(__half2*)&u; }

__global__ void agg_kernel(const __half* __restrict__ h,
                           const float* __restrict__ alpha, int M) {
    int gw = (blockIdx.x * blockDim.x + threadIdx.x) >> 5;
    if (gw >= M) return;
    int lane = threadIdx.x & 31;
    int base = lane * 4;   // halves
    float a = alpha[0];

    #pragma unroll
    for (int dir = 0; dir < 2; dir++) {
        const int* rp  = dir ? g_rp1  : g_rp0;
        const int* col = dir ? g_col1 : g_col0;
        __half* out    = dir ? g_agg1 : g_agg0;
        float coef     = dir ? a : (1.f - a);

        int s = rp[gw], e = rp[gw + 1];
        float4 acc = make_float4(0.f, 0.f, 0.f, 0.f);
        int i = s;
        for (; i + 3 < e; i += 4) {
            int n0 = col[i],     n1 = col[i + 1];
            int n2 = col[i + 2], n3 = col[i + 3];
            uint2 u0 = *(const uint2*)(h + (size_t)n0 * DD + base);
            uint2 u1 = *(const uint2*)(h + (size_t)n1 * DD + base);
            uint2 u2 = *(const uint2*)(h + (size_t)n2 * DD + base);
            uint2 u3 = *(const uint2*)(h + (size_t)n3 * DD + base);
            __half2 s0 = __hadd2(__hadd2(u2h(u0.x), u2h(u1.x)),
                                 __hadd2(u2h(u2.x), u2h(u3.x)));
            __half2 s1 = __hadd2(__hadd2(u2h(u0.y), u2h(u1.y)),
                                 __hadd2(u2h(u2.y), u2h(u3.y)));
            float2 f0 = __half22float2(s0);
            float2 f1 = __half22float2(s1);
            acc.x += f0.x; acc.y += f0.y;
            acc.z += f1.x; acc.w += f1.y;
        }
        for (; i < e; i++) {
            int n0 = col[i];
            uint2 u0 = *(const uint2*)(h + (size_t)n0 * DD + base);
            float2 f0 = __half22float2(u2h(u0.x));
            float2 f1 = __half22float2(u2h(u0.y));
            acc.x += f0.x; acc.y += f0.y;
            acc.z += f1.x; acc.w += f1.y;
        }
        float sc = coef / fmaxf((float)(e - s), 1.f);
        __half2 o0 = __floats2half2_rn(acc.x * sc, acc.y * sc);
        __half2 o1 = __floats2half2_rn(acc.z * sc, acc.w * sc);
        uint2 u;
        u.x = *(unsigned*)&o0;
        u.y = *(unsigned*)&o1;
        *(uint2*)(out + (size_t)gw * DD + base) = u;
    }
}

// ---------------- fp16 tensor-core layer GEMM (cp.async double buffer) -----
#define SA 40   // smem row stride in halves

__global__ __launch_bounds__(256) void gemm_layer_f16(
    const __half* __restrict__ A0,
    const __half* __restrict__ Wt,   // layer base (3 mats)
    const float* __restrict__ bs0,
    const float* __restrict__ bs1,
    const float* __restrict__ bs2,
    const float* __restrict__ alpha,
    __half* __restrict__ Hout,
    int firstLayer, int M)
{
    __shared__ __align__(16) __half As[2][128 * SA];
    __shared__ __align__(16) __half Bs[2][128 * SA];
    __shared__ float bias_s[DD];

    int tid = threadIdx.x;
    int block_row = blockIdx.x * 128;
    int warpId = tid >> 5;
    int lane = tid & 31;
    int g = lane >> 2;
    int t = lane & 3;
    int warp_row = warpId & 3;
    int warp_col = warpId >> 2;

    if (tid < DD) {
        float a = alpha[0];
        bias_s[tid] = bs0[tid] + (1.f - a) * bs1[tid] + a * bs2[tid];
    }

    float acc[2][8][4];
    #pragma unroll
    for (int mt = 0; mt < 2; mt++)
        #pragma unroll
        for (int nt = 0; nt < 8; nt++)
            #pragma unroll
            for (int r = 0; r < 4; r++) acc[mt][nt][r] = 0.f;

    const __half* Aseg[3] = { A0, g_agg0, g_agg1 };

    int l_row = tid >> 2;          // 0..63
    int l_kq = (tid & 3) * 8;      // halves: 0,8,16,24

    auto cp_chunk = [&](int c, int buf) {
        int seg = c >> 2;
        int kl = (c & 3) * 32;
        const __half* A = Aseg[seg];
        const __half* B = Wt + (size_t)seg * DD * DD;
        #pragma unroll
        for (int j = 0; j < 2; j++) {
            int row = l_row + j * 64;
            int gr = block_row + row;
            cp16(&As[buf][row * SA + l_kq], A + (size_t)gr * DD + kl + l_kq, gr < M);
            cp16(&Bs[buf][row * SA + l_kq], B + (size_t)row * DD + kl + l_kq, true);
        }
        asm volatile("cp.async.commit_group;");
    };

    cp_chunk(0, 0);

    #pragma unroll 1
    for (int c = 0; c < 12; c++) {
        int buf = c & 1;
        if (c < 11) {
            cp_chunk(c + 1, buf ^ 1);
            asm volatile("cp.async.wait_group 1;");
        } else {
            asm volatile("cp.async.wait_group 0;");
        }
        __syncthreads();

        #pragma unroll
        for (int ks = 0; ks < 2; ks++) {
            int k0 = ks * 16;
            unsigned af[2][4];
            #pragma unroll
            for (int mt = 0; mt < 2; mt++) {
                int mrow = warp_row * 32 + mt * 16;
                const __half* base = &As[buf][0];
                af[mt][0] = *(const unsigned*)&base[(mrow + g) * SA + k0 + 2 * t];
                af[mt][1] = *(const unsigned*)&base[(mrow + g + 8) * SA + k0 + 2 * t];
                af[mt][2] = *(const unsigned*)&base[(mrow + g) * SA + k0 + 8 + 2 * t];
                af[mt][3] = *(const unsigned*)&base[(mrow + g + 8) * SA + k0 + 8 + 2 * t];
            }
            unsigned bf[8][2];
            #pragma unroll
            for (int nt = 0; nt < 8; nt++) {
                int n = warp_col * 64 + nt * 8 + g;
                const __half* base = &Bs[buf][0];
                bf[nt][0] = *(const unsigned*)&base[n * SA + k0 + 2 * t];
                bf[nt][1] = *(const unsigned*)&base[n * SA + k0 + 8 + 2 * t];
            }
            #pragma unroll
            for (int mt = 0; mt < 2; mt++)
                #pragma unroll
                for (int nt = 0; nt < 8; nt++) {
                    asm volatile(
                        "mma.sync.aligned.m16n8k16.row.col.f32.f16.f16.f32 "
                        "{%0,%1,%2,%3}, {%4,%5,%6,%7}, {%8,%9}, {%0,%1,%2,%3};"
                        : "+f"(acc[mt][nt][0]), "+f"(acc[mt][nt][1]),
                          "+f"(acc[mt][nt][2]), "+f"(acc[mt][nt][3])
                        : "r"(af[mt][0]), "r"(af[mt][1]), "r"(af[mt][2]), "r"(af[mt][3]),
                          "r"(bf[nt][0]), "r"(bf[nt][1]));
                }
        }
        __syncthreads();
    }

    // epilogue: bias + relu + store h(fp16) + JK max(fp16)
    #pragma unroll
    for (int mt = 0; mt < 2; mt++) {
        #pragma unroll
        for (int nt = 0; nt < 8; nt++) {
            int c0 = warp_col * 64 + nt * 8 + 2 * t;
            float b0v = bias_s[c0];
            float b1v = bias_s[c0 + 1];
            #pragma unroll
            for (int rr = 0; rr < 2; rr++) {
                int r = block_row + warp_row * 32 + mt * 16 + g + rr * 8;
                if (r < M) {
                    float v0 = fmaxf(acc[mt][nt][rr * 2 + 0] + b0v, 0.f);
                    float v1 = fmaxf(acc[mt][nt][rr * 2 + 1] + b1v, 0.f);
                    __half2 hv = __floats2half2_rn(v0, v1);
                    *(__half2*)(Hout + (size_t)r * DD + c0) = hv;
                    __half2* mp = (__half2*)(g_hmax + (size_t)r * DD + c0);
                    if (firstLayer) {
                        *mp = hv;
                    } else {
                        *mp = __hmax2(*mp, hv);
                    }
                }
            }
        }
    }
}

// ---------------- final linear via fp16 MMA: hmax @ Wlt^T + blin ------------
#define SF 136   // smem stride (halves), conflict-free

__global__ __launch_bounds__(256) void final_mma_kernel(
    const float* __restrict__ blin, float* __restrict__ out, int M)
{
    extern __shared__ char dynsm[];
    float* bias_s = (float*)dynsm;                      // 256B
    __half* As = (__half*)(dynsm + 256);                // 128*136*2
    __half* Bs = As + 128 * SF;                         // 64*136*2

    int tid = threadIdx.x;
    int block_row = blockIdx.x * 128;
    int warpId = tid >> 5;
    int lane = tid & 31;
    int g = lane >> 2;
    int t = lane & 3;
    int warp_row = warpId & 3;   // 32 rows
    int warp_col = warpId >> 2;  // 32 cols

    if (tid < OO) bias_s[tid] = blin[tid];

    #pragma unroll
    for (int k = 0; k < 8; k++) {
        int idx = tid + k * 256;
        int row = idx >> 4;
        int q = (idx & 15) * 8;
        int gr = block_row + row;
        uint4 v = make_uint4(0u, 0u, 0u, 0u);
        if (gr < M) v = *(const uint4*)(g_hmax + (size_t)gr * DD + q);
        *(uint4*)&As[row * SF + q] = v;
    }
    #pragma unroll
    for (int k = 0; k < 4; k++) {
        int idx = tid + k * 256;
        int row = idx >> 4;
        int q = (idx & 15) * 8;
        *(uint4*)&Bs[row * SF + q] = *(const uint4*)(g_Wlt + row * DD + q);
    }
    __syncthreads();

    float acc[2][4][4];
    #pragma unroll
    for (int mt = 0; mt < 2; mt++)
        #pragma unroll
        for (int nt = 0; nt < 4; nt++)
            #pragma unroll
            for (int r = 0; r < 4; r++) acc[mt][nt][r] = 0.f;

    #pragma unroll
    for (int kc = 0; kc < 8; kc++) {
        int k0 = kc * 16;
        unsigned af[2][4];
        #pragma unroll
        for (int mt = 0; mt < 2; mt++) {
            int mrow = warp_row * 32 + mt * 16;
            af[mt][0] = *(const unsigned*)&As[(mrow + g) * SF + k0 + 2 * t];
            af[mt][1] = *(const unsigned*)&As[(mrow + g + 8) * SF + k0 + 2 * t];
            af[mt][2] = *(const unsigned*)&As[(mrow + g) * SF + k0 + 8 + 2 * t];
            af[mt][3] = *(const unsigned*)&As[(mrow + g + 8) * SF + k0 + 8 + 2 * t];
        }
        unsigned bf[4][2];
        #pragma unroll
        for (int nt = 0; nt < 4; nt++) {
            int n = warp_col * 32 + nt * 8 + g;
            bf[nt][0] = *(const unsigned*)&Bs[n * SF + k0 + 2 * t];
            bf[nt][1] = *(const unsigned*)&Bs[n * SF + k0 + 8 + 2 * t];
        }
        #pragma unroll
        for (int mt = 0; mt < 2; mt++)
            #pragma unroll
            for (int nt = 0; nt < 4; nt++) {
                asm volatile(
                    "mma.sync.aligned.m16n8k16.row.col.f32.f16.f16.f32 "
                    "{%0,%1,%2,%3}, {%4,%5,%6,%7}, {%8,%9}, {%0,%1,%2,%3};"
                    : "+f"(acc[mt][nt][0]), "+f"(acc[mt][nt][1]),
                      "+f"(acc[mt][nt][2]), "+f"(acc[mt][nt][3])
                    : "r"(af[mt][0]), "r"(af[mt][1]), "r"(af[mt][2]), "r"(af[mt][3]),
                      "r"(bf[nt][0]), "r"(bf[nt][1]));
            }
    }

    #pragma unroll
    for (int mt = 0; mt < 2; mt++) {
        #pragma unroll
        for (int nt = 0; nt < 4; nt++) {
            int c0 = warp_col * 32 + nt * 8 + 2 * t;
            float b0v = bias_s[c0];
            float b1v = bias_s[c0 + 1];
            #pragma unroll
            for (int rr = 0; rr < 2; rr++) {
                int r = block_row + warp_row * 32 + mt * 16 + g + rr * 8;
                if (r < M) {
                    float2 o;
                    o.x = acc[mt][nt][rr * 2 + 0] + b0v;
                    o.y = acc[mt][nt][rr * 2 + 1] + b1v;
                    *(float2*)(out + (size_t)r * OO + c0) = o;
                }
            }
        }
    }
}

// ---------------- launch ----------------
extern "C" void kernel_launch(void* const* d_in, const int* in_sizes, int n_in,
                              void* d_out, int out_size) {
    const float* x     = (const float*)d_in[0];
    const int*   ei    = (const int*)d_in[1];
    const float* Wself = (const float*)d_in[2];
    const float* bself = (const float*)d_in[3];
    const float* Wstd  = (const float*)d_in[4];
    const float* bstd  = (const float*)d_in[5];
    const float* Wdts  = (const float*)d_in[6];
    const float* bdts  = (const float*)d_in[7];
    const float* Wlin  = (const float*)d_in[8];
    const float* blin  = (const float*)d_in[9];
    const float* alpha = (const float*)d_in[10];

    int M = in_sizes[0] / DD;        // 50000
    int E = in_sizes[1] / 2;         // 800000

    __half* hx; cudaGetSymbolAddress((void**)&hx, g_hx);
    __half* h0; cudaGetSymbolAddress((void**)&h0, g_h0);
    __half* h1; cudaGetSymbolAddress((void**)&h1, g_h1);
    __half* wt; cudaGetSymbolAddress((void**)&wt, g_Wt);
    int* degp; cudaGetSymbolAddress((void**)&degp, g_deg);

    const int FINAL_SMEM = 256 + (128 * SF + 64 * SF) * 2;   // 52480
    cudaFuncSetAttribute(final_mma_kernel,
                         cudaFuncAttributeMaxDynamicSharedMemorySize, FINAL_SMEM);

    // memset node (not counted by ncu launch skip)
    cudaMemsetAsync(degp, 0, 2 * NN * sizeof(int));

    count_kernel<<<(E + 255) / 256, 256>>>(ei, E);            // launch 0
    scan_kernel<<<2, 1024>>>(M);                              // 1
    int fillBlocks = (E + 255) / 256;
    int prepBlocks = (LL * 3 * DD * DD + OO * DD + 255) / 256;
    fill_prep_kernel<<<fillBlocks + prepBlocks, 256>>>(
        ei, E, Wself, Wstd, Wdts, Wlin, fillBlocks);          // 2
    int total4 = M * DD / 4;
    convert_x_kernel<<<(total4 + 255) / 256, 256>>>(x, total4); // 3

    // layers
    const __half* cur = hx;
    __half* bufs[2] = { h0, h1 };
    int gemm_grid = (M + 127) / 128;
    int agg_grid = (M * 32 + 255) / 256;
    for (int l = 0; l < LL; l++) {
        agg_kernel<<<agg_grid, 256>>>(cur, alpha, M);         // 4 (layer 0)
        __half* outb = bufs[l & 1];
        gemm_layer_f16<<<gemm_grid, 256>>>(                   // 5 (layer 0) <- ncu
            cur,
            wt + (size_t)l * 3 * DD * DD,
            bself + (size_t)l * DD,
            bstd  + (size_t)l * DD,
            bdts  + (size_t)l * DD,
            alpha, outb, (l == 0) ? 1 : 0, M);
        cur = outb;
    }

    // final linear (fp16 MMA)
    final_mma_kernel<<<(M + 127) / 128, 256, FINAL_SMEM>>>(blin, (float*)d_out, M);
}